// round 1
// baseline (speedup 1.0000x reference)
#include <cuda_runtime.h>
#include <cuda_bf16.h>
#include <math.h>

#define B_SZ 4
#define SEQ_L 2048
#define D_MODEL 1024
#define D_INNER 2048
#define D_HALF 1024
#define D_STATE 16
#define DT_RANK 64
#define M_ROWS (B_SZ * SEQ_L)   // 8192

// ---------------- scratch (device globals; no allocation allowed) ----------
__device__ float g_xz[M_ROWS * D_INNER];     // GEMM1 out: [xs_raw | z_raw]
__device__ float g_xsc[M_ROWS * D_HALF];     // conv+silu(xs)
__device__ float g_xdbl[M_ROWS * 96];        // xs_c @ W_xdbl  (dt_low|B|C)
__device__ float g_delta[M_ROWS * D_HALF];   // softplus(dt_low@W_dt + 2*inv_dt)
__device__ float g_cat[M_ROWS * D_INNER];    // [y | conv+silu(z)]

// ---------------- generic fp32 tiled GEMM: C = A(MxK) @ B(KxN) -------------
// EPI: 0 = plain, 1 = +aux[col] (bias), 2 = softplus(acc + 2*aux[col])
template<int EPI>
__global__ __launch_bounds__(256)
void sgemm_kernel(const float* __restrict__ A, const float* __restrict__ Bm,
                  float* __restrict__ C, int M, int N, int K,
                  int lda, int ldb, int ldc, const float* __restrict__ aux)
{
    __shared__ float As[16][128];
    __shared__ float Bs[16][128];

    const int tid  = threadIdx.x;
    const int brow = blockIdx.y * 128;
    const int bcol = blockIdx.x * 128;
    const int tx = tid & 15;          // 0..15 -> col group
    const int ty = tid >> 4;          // 0..15 -> row group

    const int arow = tid >> 2;        // 0..63
    const int acol = (tid & 3) * 4;   // 0,4,8,12
    const int brw  = tid >> 5;        // 0..7
    const int bcl  = (tid & 31) * 4;  // 0..124

    float acc[8][8];
#pragma unroll
    for (int i = 0; i < 8; i++)
#pragma unroll
        for (int j = 0; j < 8; j++) acc[i][j] = 0.f;

    for (int kt = 0; kt < K; kt += 16) {
        // A tile (rows always valid: M multiple of 128; K multiple of 16)
        float4 a0 = *(const float4*)(A + (size_t)(brow + arow)      * lda + kt + acol);
        float4 a1 = *(const float4*)(A + (size_t)(brow + arow + 64) * lda + kt + acol);
        As[acol + 0][arow] = a0.x; As[acol + 1][arow] = a0.y;
        As[acol + 2][arow] = a0.z; As[acol + 3][arow] = a0.w;
        As[acol + 0][arow + 64] = a1.x; As[acol + 1][arow + 64] = a1.y;
        As[acol + 2][arow + 64] = a1.z; As[acol + 3][arow + 64] = a1.w;

        // B tile (guard columns; N always multiple of 4)
        float4 b0 = make_float4(0.f, 0.f, 0.f, 0.f);
        float4 b1 = make_float4(0.f, 0.f, 0.f, 0.f);
        if (bcol + bcl < N) {
            b0 = *(const float4*)(Bm + (size_t)(kt + brw)     * ldb + bcol + bcl);
            b1 = *(const float4*)(Bm + (size_t)(kt + brw + 8) * ldb + bcol + bcl);
        }
        *(float4*)&Bs[brw][bcl]     = b0;
        *(float4*)&Bs[brw + 8][bcl] = b1;

        __syncthreads();

#pragma unroll
        for (int k = 0; k < 16; k++) {
            float av[8], bv[8];
            *(float4*)(av)     = *(const float4*)&As[k][ty * 8];
            *(float4*)(av + 4) = *(const float4*)&As[k][ty * 8 + 4];
            *(float4*)(bv)     = *(const float4*)&Bs[k][tx * 8];
            *(float4*)(bv + 4) = *(const float4*)&Bs[k][tx * 8 + 4];
#pragma unroll
            for (int i = 0; i < 8; i++)
#pragma unroll
                for (int j = 0; j < 8; j++)
                    acc[i][j] = fmaf(av[i], bv[j], acc[i][j]);
        }
        __syncthreads();
    }

#pragma unroll
    for (int i = 0; i < 8; i++) {
        int row = brow + ty * 8 + i;
#pragma unroll
        for (int j = 0; j < 8; j++) {
            int col = bcol + tx * 8 + j;
            if (col < N) {
                float v = acc[i][j];
                if (EPI == 1) v += aux[col];
                if (EPI == 2) {
                    v += 2.f * aux[col];
                    v = (v > 20.f) ? v : log1pf(__expf(v));   // softplus
                }
                C[(size_t)row * ldc + col] = v;
            }
        }
    }
}

// ---------------- depthwise conv (k=4, SAME: pad lo=1 hi=2) + SiLU ---------
__global__ __launch_bounds__(256)
void dwconv_silu_kernel(const float* __restrict__ src, int src_ld,
                        const float* __restrict__ w, const float* __restrict__ bias,
                        float* __restrict__ dst, int dst_ld)
{
    int idx = blockIdx.x * blockDim.x + threadIdx.x;
    if (idx >= B_SZ * SEQ_L * D_HALF) return;
    int c = idx & (D_HALF - 1);
    int t = (idx >> 10) & (SEQ_L - 1);
    int b = idx >> 21;

    const float* srow = src + (size_t)b * SEQ_L * src_ld + c;
    float acc = bias[c];
#pragma unroll
    for (int j = 0; j < 4; j++) {
        int tt = t - 1 + j;
        if (tt >= 0 && tt < SEQ_L)
            acc = fmaf(srow[(size_t)tt * src_ld], w[j * D_HALF + c], acc);
    }
    float s = acc * (1.f / (1.f + __expf(-acc)));   // silu
    dst[(size_t)b * SEQ_L * dst_ld + (size_t)t * dst_ld + c] = s;
}

// ---------------- selective scan -------------------------------------------
// A[d,n] = -(n+1)  ->  dA_n = exp(-delta)^(n+1)
// One thread per (b,d) channel; 16 states in registers.
// B/C staged in double-buffered SMEM per group of 4 timesteps; delta/u
// software-pipelined one group (4 steps) ahead.
__global__ __launch_bounds__(128)
void scan_kernel(const float* __restrict__ delta,
                 const float* __restrict__ u,
                 const float* __restrict__ xdbl,
                 const float* __restrict__ Dp,
                 float* __restrict__ ycat)
{
    int b = blockIdx.x >> 3;                              // 0..3
    int d = ((blockIdx.x & 7) << 7) + threadIdx.x;        // 0..1023

    const float* dptr = delta + (size_t)b * SEQ_L * D_HALF + d;
    const float* uptr = u     + (size_t)b * SEQ_L * D_HALF + d;
    const float* bc   = xdbl  + (size_t)b * SEQ_L * 96 + DT_RANK;  // B@+0, C@+16
    float*       yptr = ycat  + (size_t)b * SEQ_L * D_INNER + d;

    __shared__ float sBC[2][4][32];   // [buf][step-in-group][16 B | 16 C]

    float h[16];
#pragma unroll
    for (int n = 0; n < 16; n++) h[n] = 0.f;
    float Dd = Dp[d];

    // preload group 0
    {
        int j = threadIdx.x >> 5, v = threadIdx.x & 31;
        sBC[0][j][v] = bc[(size_t)j * 96 + v];
    }
    float dl[4], uu[4];
#pragma unroll
    for (int j = 0; j < 4; j++) {
        dl[j] = dptr[(size_t)j * D_HALF];
        uu[j] = uptr[(size_t)j * D_HALF];
    }
    __syncthreads();

    for (int tg = 0; tg < SEQ_L; tg += 4) {
        int cb = (tg >> 2) & 1, nb = cb ^ 1;
        float dl2[4] = {0.f, 0.f, 0.f, 0.f}, uu2[4] = {0.f, 0.f, 0.f, 0.f};
        if (tg + 4 < SEQ_L) {
            int j = threadIdx.x >> 5, v = threadIdx.x & 31;
            sBC[nb][j][v] = bc[(size_t)(tg + 4 + j) * 96 + v];
#pragma unroll
            for (int j2 = 0; j2 < 4; j2++) {
                dl2[j2] = dptr[(size_t)(tg + 4 + j2) * D_HALF];
                uu2[j2] = uptr[(size_t)(tg + 4 + j2) * D_HALF];
            }
        }
#pragma unroll
        for (int j = 0; j < 4; j++) {
            float del = dl[j], uv = uu[j];
            float e1 = __expf(-del);
            float e2 = e1 * e1;
            float e3 = e2 * e1;
            float e4 = e2 * e2;
            float dbu = del * uv;
            const float* Bv = sBC[cb][j];
            float a0 = 0.f, a1 = 0.f, a2 = 0.f, a3 = 0.f;
            float pw = 1.f;
#pragma unroll
            for (int g = 0; g < 4; g++) {
                float q1 = pw * e1, q2 = pw * e2, q3 = pw * e3, q4 = pw * e4;
                int n = g * 4;
                h[n]     = fmaf(q1, h[n],     dbu * Bv[n]);     a0 = fmaf(h[n],     Bv[16 + n],     a0);
                h[n + 1] = fmaf(q2, h[n + 1], dbu * Bv[n + 1]); a1 = fmaf(h[n + 1], Bv[16 + n + 1], a1);
                h[n + 2] = fmaf(q3, h[n + 2], dbu * Bv[n + 2]); a2 = fmaf(h[n + 2], Bv[16 + n + 2], a2);
                h[n + 3] = fmaf(q4, h[n + 3], dbu * Bv[n + 3]); a3 = fmaf(h[n + 3], Bv[16 + n + 3], a3);
                pw = q4;
            }
            yptr[(size_t)(tg + j) * D_INNER] = (a0 + a1) + (a2 + a3) + uv * Dd;
        }
#pragma unroll
        for (int j = 0; j < 4; j++) { dl[j] = dl2[j]; uu[j] = uu2[j]; }
        __syncthreads();
    }
}

// ---------------- launch ----------------------------------------------------
extern "C" void kernel_launch(void* const* d_in, const int* in_sizes, int n_in,
                              void* d_out, int out_size)
{
    const float* x       = (const float*)d_in[0];
    const float* W_in    = (const float*)d_in[1];
    const float* conv_xw = (const float*)d_in[2];
    const float* conv_xb = (const float*)d_in[3];
    const float* conv_zw = (const float*)d_in[4];
    const float* conv_zb = (const float*)d_in[5];
    const float* W_xdbl  = (const float*)d_in[6];
    const float* W_dt    = (const float*)d_in[7];
    const float* inv_dt  = (const float*)d_in[8];
    const float* Dp      = (const float*)d_in[9];
    const float* W_out   = (const float*)d_in[10];
    const float* b_out   = (const float*)d_in[11];
    float* out = (float*)d_out;

    float *p_xz, *p_xsc, *p_xdbl, *p_delta, *p_cat;
    cudaGetSymbolAddress((void**)&p_xz,    g_xz);
    cudaGetSymbolAddress((void**)&p_xsc,   g_xsc);
    cudaGetSymbolAddress((void**)&p_xdbl,  g_xdbl);
    cudaGetSymbolAddress((void**)&p_delta, g_delta);
    cudaGetSymbolAddress((void**)&p_cat,   g_cat);

    // 1) xz = x @ W_in                       (8192 x 2048, K=1024)
    sgemm_kernel<0><<<dim3(D_INNER / 128, M_ROWS / 128), 256>>>(
        x, W_in, p_xz, M_ROWS, D_INNER, D_MODEL, D_MODEL, D_INNER, D_INNER, nullptr);

    // 2) xs_c = silu(dwconv(xs)); z_c = silu(dwconv(z)) -> cat[:,1024:]
    int nconv = B_SZ * SEQ_L * D_HALF;
    dwconv_silu_kernel<<<(nconv + 255) / 256, 256>>>(
        p_xz, D_INNER, conv_xw, conv_xb, p_xsc, D_HALF);
    dwconv_silu_kernel<<<(nconv + 255) / 256, 256>>>(
        p_xz + D_HALF, D_INNER, conv_zw, conv_zb, p_cat + D_HALF, D_INNER);

    // 3) x_dbl = xs_c @ W_xdbl              (8192 x 96, K=1024)
    sgemm_kernel<0><<<dim3(1, M_ROWS / 128), 256>>>(
        p_xsc, W_xdbl, p_xdbl, M_ROWS, 96, D_HALF, D_HALF, 96, 96, nullptr);

    // 4) delta = softplus(dt_low @ W_dt + 2*inv_dt)   (8192 x 1024, K=64)
    sgemm_kernel<2><<<dim3(D_HALF / 128, M_ROWS / 128), 256>>>(
        p_xdbl, W_dt, p_delta, M_ROWS, D_HALF, DT_RANK, 96, D_HALF, D_HALF, inv_dt);

    // 5) selective scan -> cat[:, :1024]
    scan_kernel<<<B_SZ * (D_HALF / 128), 128>>>(p_delta, p_xsc, p_xdbl, Dp, p_cat);

    // 6) out = cat @ W_out + b_out          (8192 x 1024, K=2048)
    sgemm_kernel<1><<<dim3(D_MODEL / 128, M_ROWS / 128), 256>>>(
        p_cat, W_out, out, M_ROWS, D_MODEL, D_INNER, D_INNER, D_MODEL, D_MODEL, b_out);
}

// round 4
// speedup vs baseline: 1.3363x; 1.3363x over previous
#include <cuda_runtime.h>
#include <cuda_bf16.h>
#include <math.h>
#include <stdint.h>

#define B_SZ 4
#define SEQ_L 2048
#define D_MODEL 1024
#define D_INNER 2048
#define D_HALF 1024
#define D_STATE 16
#define DT_RANK 64
#define M_ROWS (B_SZ * SEQ_L)   // 8192

// ---------------- scratch (device globals; no allocation allowed) ----------
__device__ float g_xz[M_ROWS * D_INNER];      // GEMM1 out: [xs_raw | z_raw]
__device__ float g_xsc[M_ROWS * D_HALF];      // conv+silu(xs)
__device__ float g_xdbl[M_ROWS * 96];         // xs_c @ W_xdbl  (dt_low|B|C)
__device__ float g_delta[M_ROWS * D_HALF];    // softplus(...)
__device__ float g_cat[M_ROWS * D_INNER];     // [y | conv+silu(z)]

// ============================ helpers ======================================
__device__ __forceinline__ uint32_t smem_u32(const void* p) {
    uint32_t a;
    asm("{ .reg .u64 t; cvta.to.shared.u64 t, %1; cvt.u32.u64 %0, t; }"
        : "=r"(a) : "l"(p));
    return a;
}

__device__ __forceinline__ uint32_t f2tf32(float f) {
    uint32_t r;
    asm("cvt.rna.tf32.f32 %0, %1;" : "=r"(r) : "f"(f));
    return r;
}

__device__ __forceinline__ void mma8(float* c, const uint32_t* a, const uint32_t* b) {
    asm volatile(
        "mma.sync.aligned.m16n8k8.row.col.f32.tf32.tf32.f32 "
        "{%0,%1,%2,%3}, {%4,%5,%6,%7}, {%8,%9}, {%0,%1,%2,%3};"
        : "+f"(c[0]), "+f"(c[1]), "+f"(c[2]), "+f"(c[3])
        : "r"(a[0]), "r"(a[1]), "r"(a[2]), "r"(a[3]), "r"(b[0]), "r"(b[1]));
}

// ============================ tf32 mma.sync GEMM ===========================
// C[M,N] = A[M,K] @ B[K,N] (+ aux per EPI).  A row-major lda=K, B row-major
// ldb=N, C row-major ldc=N.  CTA tile 128x128, K-tile 32, 2-stage cp.async.
// EPI: 0 = plain, 1 = +aux[col].  NG: guard N (tile cols may exceed N).
#define SREG 136                       // smem row stride (floats): 136%32==8
#define ATILE (32 * SREG)              // 4352 floats per A stage
#define STG   (2 * ATILE)              // floats per stage (A + B)

template<int EPI, bool NG>
__global__ __launch_bounds__(256)
void mma_gemm(const float* __restrict__ A, const float* __restrict__ B,
              float* __restrict__ C, int M, int N, int K,
              const float* __restrict__ aux)
{
    extern __shared__ float sm[];      // [2][A(32x136) | B(32x136)]

    const int tid  = threadIdx.x;
    const int wid  = tid >> 5;
    const int lane = tid & 31;
    const int g    = lane >> 2;        // 0..7
    const int t4   = lane & 3;         // 0..3
    const int wm   = wid & 1;          // warp row (2)
    const int wn   = wid >> 1;         // warp col (4)

    const int brow = blockIdx.y * 128;
    const int bcol = blockIdx.x * 128;
    const int NT   = K >> 5;

    // A ldg mapping: thread covers (row = tid&127, kseg = (tid>>7)*16)
    const int arow = tid & 127;
    const int kseg = (tid >> 7) * 16;
    const float* gA = A + (size_t)(brow + arow) * K + kseg;

    float acc[4][4][4];
#pragma unroll
    for (int i = 0; i < 4; i++)
#pragma unroll
        for (int j = 0; j < 4; j++)
#pragma unroll
            for (int c = 0; c < 4; c++) acc[i][j][c] = 0.f;

    float abuf[16];

    auto ldgA = [&](int kt) {
#pragma unroll
        for (int i = 0; i < 4; i++)
            *(float4*)(abuf + 4 * i) =
                *(const float4*)(gA + (size_t)kt * 32 + 4 * i);
    };
    auto stsA = [&](int stage) {
        uint32_t* dst = (uint32_t*)(sm + stage * STG);
#pragma unroll
        for (int j = 0; j < 16; j++)
            dst[(kseg + j) * SREG + arow] = f2tf32(abuf[j]);
    };
    auto cpB = [&](int stage, int kt) {
        float* dstb = sm + stage * STG + ATILE;
#pragma unroll
        for (int i = 0; i < 4; i++) {
            int c  = tid + i * 256;
            int rw = c >> 5;
            int cl = (c & 31) * 4;
            const float* src = B + (size_t)(kt * 32 + rw) * N + bcol + cl;
            uint32_t da = smem_u32(dstb + rw * SREG + cl);
            int sz = (!NG || (bcol + cl) < N) ? 16 : 0;
            asm volatile("cp.async.cg.shared.global [%0], [%1], 16, %2;"
                         :: "r"(da), "l"(src), "r"(sz));
        }
    };
    auto compute = [&](int stage) {
        const uint32_t* asu = (const uint32_t*)(sm + stage * STG);
        const float*    bsf = sm + stage * STG + ATILE;
#pragma unroll
        for (int kk = 0; kk < 4; kk++) {
            int kr = kk * 8 + t4;
            uint32_t af[4][4];
#pragma unroll
            for (int mt = 0; mt < 4; mt++) {
                int m0 = wm * 64 + mt * 16 + g;
                af[mt][0] = asu[kr * SREG + m0];
                af[mt][1] = asu[kr * SREG + m0 + 8];
                af[mt][2] = asu[(kr + 4) * SREG + m0];
                af[mt][3] = asu[(kr + 4) * SREG + m0 + 8];
            }
            uint32_t bf[4][2];
#pragma unroll
            for (int nt = 0; nt < 4; nt++) {
                int n0 = wn * 32 + nt * 8 + g;
                bf[nt][0] = f2tf32(bsf[kr * SREG + n0]);
                bf[nt][1] = f2tf32(bsf[(kr + 4) * SREG + n0]);
            }
#pragma unroll
            for (int mt = 0; mt < 4; mt++)
#pragma unroll
                for (int nt = 0; nt < 4; nt++)
                    mma8(acc[mt][nt], af[mt], bf[nt]);
        }
    };

    // prologue: tile 0
    ldgA(0);
    cpB(0, 0);
    asm volatile("cp.async.commit_group;");
    stsA(0);
    asm volatile("cp.async.wait_group 0;");
    __syncthreads();

    for (int kt = 0; kt < NT; kt++) {
        int nxt = kt + 1;
        if (nxt < NT) {
            ldgA(nxt);
            cpB(nxt & 1, nxt);
            asm volatile("cp.async.commit_group;");
        }
        compute(kt & 1);
        if (nxt < NT) {
            stsA(nxt & 1);
            asm volatile("cp.async.wait_group 0;");
        }
        __syncthreads();
    }

    // epilogue
#pragma unroll
    for (int mt = 0; mt < 4; mt++) {
        int r0 = brow + wm * 64 + mt * 16 + g;
#pragma unroll
        for (int nt = 0; nt < 4; nt++) {
            int col = bcol + wn * 32 + nt * 8 + 2 * t4;
            if (!NG || col < N) {
                float2 v0 = make_float2(acc[mt][nt][0], acc[mt][nt][1]);
                float2 v1 = make_float2(acc[mt][nt][2], acc[mt][nt][3]);
                if (EPI == 1) {
                    float2 ax = *(const float2*)(aux + col);
                    v0.x += ax.x; v0.y += ax.y;
                    v1.x += ax.x; v1.y += ax.y;
                }
                *(float2*)(C + (size_t)r0 * N + col)       = v0;
                *(float2*)(C + (size_t)(r0 + 8) * N + col) = v1;
            }
        }
    }
}

// ============================ fp32 SIMT GEMM (dt path) =====================
// EPI 2 = softplus(acc + 2*aux[col])
template<int EPI>
__global__ __launch_bounds__(256)
void sgemm_kernel(const float* __restrict__ A, const float* __restrict__ Bm,
                  float* __restrict__ C, int M, int N, int K,
                  int lda, int ldb, int ldc, const float* __restrict__ aux)
{
    __shared__ float As[16][128];
    __shared__ float Bs[16][128];

    const int tid  = threadIdx.x;
    const int brow = blockIdx.y * 128;
    const int bcol = blockIdx.x * 128;
    const int tx = tid & 15;
    const int ty = tid >> 4;

    const int arow = tid >> 2;
    const int acol = (tid & 3) * 4;
    const int brw  = tid >> 5;
    const int bcl  = (tid & 31) * 4;

    float acc[8][8];
#pragma unroll
    for (int i = 0; i < 8; i++)
#pragma unroll
        for (int j = 0; j < 8; j++) acc[i][j] = 0.f;

    for (int kt = 0; kt < K; kt += 16) {
        float4 a0 = *(const float4*)(A + (size_t)(brow + arow)      * lda + kt + acol);
        float4 a1 = *(const float4*)(A + (size_t)(brow + arow + 64) * lda + kt + acol);
        As[acol + 0][arow] = a0.x; As[acol + 1][arow] = a0.y;
        As[acol + 2][arow] = a0.z; As[acol + 3][arow] = a0.w;
        As[acol + 0][arow + 64] = a1.x; As[acol + 1][arow + 64] = a1.y;
        As[acol + 2][arow + 64] = a1.z; As[acol + 3][arow + 64] = a1.w;

        float4 b0 = *(const float4*)(Bm + (size_t)(kt + brw)     * ldb + bcol + bcl);
        float4 b1 = *(const float4*)(Bm + (size_t)(kt + brw + 8) * ldb + bcol + bcl);
        *(float4*)&Bs[brw][bcl]     = b0;
        *(float4*)&Bs[brw + 8][bcl] = b1;

        __syncthreads();

#pragma unroll
        for (int k = 0; k < 16; k++) {
            float av[8], bv[8];
            *(float4*)(av)     = *(const float4*)&As[k][ty * 8];
            *(float4*)(av + 4) = *(const float4*)&As[k][ty * 8 + 4];
            *(float4*)(bv)     = *(const float4*)&Bs[k][tx * 8];
            *(float4*)(bv + 4) = *(const float4*)&Bs[k][tx * 8 + 4];
#pragma unroll
            for (int i = 0; i < 8; i++)
#pragma unroll
                for (int j = 0; j < 8; j++)
                    acc[i][j] = fmaf(av[i], bv[j], acc[i][j]);
        }
        __syncthreads();
    }

#pragma unroll
    for (int i = 0; i < 8; i++) {
        int rw = brow + ty * 8 + i;
#pragma unroll
        for (int j = 0; j < 8; j++) {
            int col = bcol + tx * 8 + j;
            float v = acc[i][j];
            if (EPI == 2) {
                v += 2.f * aux[col];
                v = (v > 20.f) ? v : log1pf(__expf(v));
            }
            C[(size_t)rw * ldc + col] = v;
        }
    }
}

// ---------------- depthwise conv (k=4, SAME: pad lo=1 hi=2) + SiLU ---------
__global__ __launch_bounds__(256)
void dwconv_silu_kernel(const float* __restrict__ src, int src_ld,
                        const float* __restrict__ w, const float* __restrict__ bias,
                        float* __restrict__ dst, int dst_ld)
{
    int idx = blockIdx.x * blockDim.x + threadIdx.x;
    if (idx >= B_SZ * SEQ_L * D_HALF) return;
    int c = idx & (D_HALF - 1);
    int t = (idx >> 10) & (SEQ_L - 1);
    int b = idx >> 21;

    const float* srow = src + (size_t)b * SEQ_L * src_ld + c;
    float acc = bias[c];
#pragma unroll
    for (int j = 0; j < 4; j++) {
        int tt = t - 1 + j;
        if (tt >= 0 && tt < SEQ_L)
            acc = fmaf(srow[(size_t)tt * src_ld], w[j * D_HALF + c], acc);
    }
    float s = acc * (1.f / (1.f + __expf(-acc)));
    dst[(size_t)b * SEQ_L * dst_ld + (size_t)t * dst_ld + c] = s;
}

// ---------------- selective scan (32-thread blocks, 128 blocks) ------------
__global__ __launch_bounds__(32)
void scan_kernel(const float* __restrict__ delta,
                 const float* __restrict__ u,
                 const float* __restrict__ xdbl,
                 const float* __restrict__ Dp,
                 float* __restrict__ ycat)
{
    int b = blockIdx.x >> 5;                              // 0..3
    int d = ((blockIdx.x & 31) << 5) + threadIdx.x;       // 0..1023

    const float* dptr = delta + (size_t)b * SEQ_L * D_HALF + d;
    const float* uptr = u     + (size_t)b * SEQ_L * D_HALF + d;
    const float* bc   = xdbl  + (size_t)b * SEQ_L * 96 + DT_RANK;
    float*       yptr = ycat  + (size_t)b * SEQ_L * D_INNER + d;

    __shared__ float sBC[2][4][32];

    float h[16];
#pragma unroll
    for (int n = 0; n < 16; n++) h[n] = 0.f;
    float Dd = Dp[d];

    for (int e = threadIdx.x; e < 128; e += 32)
        sBC[0][e >> 5][e & 31] = bc[(size_t)(e >> 5) * 96 + (e & 31)];
    float dl[4], uu[4];
#pragma unroll
    for (int j = 0; j < 4; j++) {
        dl[j] = dptr[(size_t)j * D_HALF];
        uu[j] = uptr[(size_t)j * D_HALF];
    }
    __syncwarp();

    for (int tg = 0; tg < SEQ_L; tg += 4) {
        int cb = (tg >> 2) & 1, nb = cb ^ 1;
        float dl2[4] = {0.f, 0.f, 0.f, 0.f}, uu2[4] = {0.f, 0.f, 0.f, 0.f};
        if (tg + 4 < SEQ_L) {
            for (int e = threadIdx.x; e < 128; e += 32)
                sBC[nb][e >> 5][e & 31] = bc[(size_t)(tg + 4 + (e >> 5)) * 96 + (e & 31)];
#pragma unroll
            for (int j2 = 0; j2 < 4; j2++) {
                dl2[j2] = dptr[(size_t)(tg + 4 + j2) * D_HALF];
                uu2[j2] = uptr[(size_t)(tg + 4 + j2) * D_HALF];
            }
        }
#pragma unroll
        for (int j = 0; j < 4; j++) {
            float del = dl[j], uv = uu[j];
            float e1 = __expf(-del);
            float e2 = e1 * e1;
            float e3 = e2 * e1;
            float e4 = e2 * e2;
            float dbu = del * uv;
            const float* Bv = sBC[cb][j];
            float a0 = 0.f, a1 = 0.f, a2 = 0.f, a3 = 0.f;
            float pw = 1.f;
#pragma unroll
            for (int gg = 0; gg < 4; gg++) {
                float q1 = pw * e1, q2 = pw * e2, q3 = pw * e3, q4 = pw * e4;
                int n = gg * 4;
                h[n]     = fmaf(q1, h[n],     dbu * Bv[n]);     a0 = fmaf(h[n],     Bv[16 + n],     a0);
                h[n + 1] = fmaf(q2, h[n + 1], dbu * Bv[n + 1]); a1 = fmaf(h[n + 1], Bv[16 + n + 1], a1);
                h[n + 2] = fmaf(q3, h[n + 2], dbu * Bv[n + 2]); a2 = fmaf(h[n + 2], Bv[16 + n + 2], a2);
                h[n + 3] = fmaf(q4, h[n + 3], dbu * Bv[n + 3]); a3 = fmaf(h[n + 3], Bv[16 + n + 3], a3);
                pw = q4;
            }
            yptr[(size_t)(tg + j) * D_INNER] = (a0 + a1) + (a2 + a3) + uv * Dd;
        }
#pragma unroll
        for (int j = 0; j < 4; j++) { dl[j] = dl2[j]; uu[j] = uu2[j]; }
        __syncwarp();
    }
}

// ---------------- launch ----------------------------------------------------
extern "C" void kernel_launch(void* const* d_in, const int* in_sizes, int n_in,
                              void* d_out, int out_size)
{
    const float* x       = (const float*)d_in[0];
    const float* W_in    = (const float*)d_in[1];
    const float* conv_xw = (const float*)d_in[2];
    const float* conv_xb = (const float*)d_in[3];
    const float* conv_zw = (const float*)d_in[4];
    const float* conv_zb = (const float*)d_in[5];
    const float* W_xdbl  = (const float*)d_in[6];
    const float* W_dt    = (const float*)d_in[7];
    const float* inv_dt  = (const float*)d_in[8];
    const float* Dp      = (const float*)d_in[9];
    const float* W_out   = (const float*)d_in[10];
    const float* b_out   = (const float*)d_in[11];
    float* out = (float*)d_out;

    float *p_xz, *p_xsc, *p_xdbl, *p_delta, *p_cat;
    cudaGetSymbolAddress((void**)&p_xz,    g_xz);
    cudaGetSymbolAddress((void**)&p_xsc,   g_xsc);
    cudaGetSymbolAddress((void**)&p_xdbl,  g_xdbl);
    cudaGetSymbolAddress((void**)&p_delta, g_delta);
    cudaGetSymbolAddress((void**)&p_cat,   g_cat);

    const int SMEM = 2 * STG * 4;   // 2 stages * (A+B) floats * 4B = 69632
    cudaFuncSetAttribute(mma_gemm<0, false>, cudaFuncAttributeMaxDynamicSharedMemorySize, SMEM);
    cudaFuncSetAttribute(mma_gemm<1, false>, cudaFuncAttributeMaxDynamicSharedMemorySize, SMEM);
    cudaFuncSetAttribute(mma_gemm<0, true>,  cudaFuncAttributeMaxDynamicSharedMemorySize, SMEM);

    // 1) xz = x @ W_in   (8192 x 2048, K=1024)
    mma_gemm<0, false><<<dim3(D_INNER / 128, M_ROWS / 128), 256, SMEM>>>(
        x, W_in, p_xz, M_ROWS, D_INNER, D_MODEL, nullptr);

    // 2) convs + silu
    int nconv = B_SZ * SEQ_L * D_HALF;
    dwconv_silu_kernel<<<(nconv + 255) / 256, 256>>>(
        p_xz, D_INNER, conv_xw, conv_xb, p_xsc, D_HALF);
    dwconv_silu_kernel<<<(nconv + 255) / 256, 256>>>(
        p_xz + D_HALF, D_INNER, conv_zw, conv_zb, p_cat + D_HALF, D_INNER);

    // 3) x_dbl = xs_c @ W_xdbl   (8192 x 96, K=1024)
    mma_gemm<0, true><<<dim3(1, M_ROWS / 128), 256, SMEM>>>(
        p_xsc, W_xdbl, p_xdbl, M_ROWS, 96, D_HALF, nullptr);

    // 4) delta = softplus(dt_low @ W_dt + 2*inv_dt)   (8192 x 1024, K=64)
    sgemm_kernel<2><<<dim3(D_HALF / 128, M_ROWS / 128), 256>>>(
        p_xdbl, W_dt, p_delta, M_ROWS, D_HALF, DT_RANK, 96, D_HALF, D_HALF, inv_dt);

    // 5) selective scan -> cat[:, :1024]
    scan_kernel<<<B_SZ * 32, 32>>>(p_delta, p_xsc, p_xdbl, Dp, p_cat);

    // 6) out = cat @ W_out + b_out   (8192 x 1024, K=2048)
    mma_gemm<1, false><<<dim3(D_MODEL / 128, M_ROWS / 128), 256, SMEM>>>(
        p_cat, W_out, out, M_ROWS, D_MODEL, D_INNER, b_out);
}

// round 9
// speedup vs baseline: 1.6405x; 1.2276x over previous
#include <cuda_runtime.h>
#include <cuda_bf16.h>
#include <math.h>
#include <stdint.h>

#define B_SZ 4
#define SEQ_L 2048
#define D_MODEL 1024
#define D_INNER 2048
#define D_HALF 1024
#define D_STATE 16
#define DT_RANK 64
#define M_ROWS (B_SZ * SEQ_L)   // 8192

// ---------------- scratch (device globals; no allocation allowed) ----------
__device__ float g_xz[M_ROWS * D_INNER];      // GEMM1 out: [xs_raw | z_raw]
__device__ float g_xsc[M_ROWS * D_HALF];      // conv+silu(xs)
__device__ float g_xdbl[M_ROWS * 96];         // xs_c @ W_xdbl  (dt_low|B|C)
__device__ float g_delta[M_ROWS * D_HALF];    // softplus(...)
__device__ float g_cat[M_ROWS * D_INNER];     // [y | conv+silu(z)]

// ============================ helpers ======================================
__device__ __forceinline__ uint32_t smem_u32(const void* p) {
    uint32_t a;
    asm("{ .reg .u64 t; cvta.to.shared.u64 t, %1; cvt.u32.u64 %0, t; }"
        : "=r"(a) : "l"(p));
    return a;
}

__device__ __forceinline__ uint32_t f2tf32(float f) {
    uint32_t r;
    asm("cvt.rna.tf32.f32 %0, %1;" : "=r"(r) : "f"(f));
    return r;
}

__device__ __forceinline__ void mma8(float* c, const uint32_t* a, const uint32_t* b) {
    asm volatile(
        "mma.sync.aligned.m16n8k8.row.col.f32.tf32.tf32.f32 "
        "{%0,%1,%2,%3}, {%4,%5,%6,%7}, {%8,%9}, {%0,%1,%2,%3};"
        : "+f"(c[0]), "+f"(c[1]), "+f"(c[2]), "+f"(c[3])
        : "r"(a[0]), "r"(a[1]), "r"(a[2]), "r"(a[3]), "r"(b[0]), "r"(b[1]));
}

// ===================== big tf32 mma GEMM: 256x128 CTA ======================
// C[M,N] = A[M,K] @ B[K,N].  A row-major (lda), B row-major (ldb=N).
// CTA 256x128, warp tile 64x64 (8 warps = 4 wm x 2 wn), BK=16, 4 stages.
// EPI: 0 plain, 1 +aux[col], 2 softplus(acc + 2*aux[col]).
template<int EPI>
__global__ __launch_bounds__(256)
void mma_gemm_big(const float* __restrict__ A, const float* __restrict__ B,
                  float* __restrict__ C, int M, int N, int K,
                  int lda, const float* __restrict__ aux)
{
    constexpr int BM = 256, BN = 128, BK = 16, STAGES = 4;
    constexpr int ASTR = 20;                 // A smem row stride (floats)
    constexpr int BSTR = 136;                // B smem row stride (floats)
    constexpr int AFL  = BM * ASTR;          // 5120
    constexpr int BFL  = BK * BSTR;          // 2176
    constexpr int STGF = AFL + BFL;          // 7296 floats / stage

    extern __shared__ float sm[];

    const int tid  = threadIdx.x;
    const int wid  = tid >> 5;
    const int lane = tid & 31;
    const int g    = lane >> 2;
    const int t4   = lane & 3;
    const int wm   = wid & 3;                // 4 warp rows
    const int wn   = wid >> 2;               // 2 warp cols

    const int brow = blockIdx.y * BM;
    const int bcol = blockIdx.x * BN;
    const int NT   = K / BK;

    float acc[4][8][4];
#pragma unroll
    for (int i = 0; i < 4; i++)
#pragma unroll
        for (int j = 0; j < 8; j++)
#pragma unroll
            for (int c = 0; c < 4; c++) acc[i][j][c] = 0.f;

    auto load_stage = [&](int s, int kt) {
        float* sa = sm + s * STGF;
        float* sb = sa + AFL;
        // A: 256 rows x 16 floats = 1024 16B chunks
#pragma unroll
        for (int i = 0; i < 4; i++) {
            int c  = tid + i * 256;
            int rw = c >> 2, ks = (c & 3) * 4;
            const float* src = A + (size_t)(brow + rw) * lda + kt * BK + ks;
            uint32_t da = smem_u32(sa + rw * ASTR + ks);
            asm volatile("cp.async.cg.shared.global [%0], [%1], 16;"
                         :: "r"(da), "l"(src));
        }
        // B: 16 rows x 128 floats = 512 chunks
#pragma unroll
        for (int i = 0; i < 2; i++) {
            int c  = tid + i * 256;
            int rw = c >> 5, cl = (c & 31) * 4;
            const float* src = B + (size_t)(kt * BK + rw) * N + bcol + cl;
            uint32_t da = smem_u32(sb + rw * BSTR + cl);
            asm volatile("cp.async.cg.shared.global [%0], [%1], 16;"
                         :: "r"(da), "l"(src));
        }
        asm volatile("cp.async.commit_group;");
    };

    auto compute = [&](int s) {
        const float* sa = sm + s * STGF;
        const float* sb = sa + AFL;
#pragma unroll
        for (int kk = 0; kk < 2; kk++) {
            int k0 = kk * 8;
            uint32_t af[4][4];
#pragma unroll
            for (int mt = 0; mt < 4; mt++) {
                int m0 = wm * 64 + mt * 16 + g;
                af[mt][0] = f2tf32(sa[(size_t)m0 * ASTR + k0 + t4]);
                af[mt][1] = f2tf32(sa[(size_t)(m0 + 8) * ASTR + k0 + t4]);
                af[mt][2] = f2tf32(sa[(size_t)m0 * ASTR + k0 + t4 + 4]);
                af[mt][3] = f2tf32(sa[(size_t)(m0 + 8) * ASTR + k0 + t4 + 4]);
            }
            uint32_t bf[8][2];
#pragma unroll
            for (int nt = 0; nt < 8; nt++) {
                int n0 = wn * 64 + nt * 8 + g;
                bf[nt][0] = f2tf32(sb[(size_t)(k0 + t4) * BSTR + n0]);
                bf[nt][1] = f2tf32(sb[(size_t)(k0 + t4 + 4) * BSTR + n0]);
            }
#pragma unroll
            for (int mt = 0; mt < 4; mt++)
#pragma unroll
                for (int nt = 0; nt < 8; nt++)
                    mma8(acc[mt][nt], af[mt], bf[nt]);
        }
    };

    // prologue: stages 0..2  (NT >= 4 for all call sites)
    for (int s = 0; s < STAGES - 1; s++) load_stage(s, s);

    for (int kt = 0; kt < NT; kt++) {
        asm volatile("cp.async.wait_group 2;");
        __syncthreads();
        int kp = kt + STAGES - 1;
        if (kp < NT) load_stage(kp & 3, kp);
        else asm volatile("cp.async.commit_group;");
        compute(kt & 3);
    }

    // epilogue
#pragma unroll
    for (int mt = 0; mt < 4; mt++) {
        int r0 = brow + wm * 64 + mt * 16 + g;
#pragma unroll
        for (int nt = 0; nt < 8; nt++) {
            int col = bcol + wn * 64 + nt * 8 + 2 * t4;
            float2 v0 = make_float2(acc[mt][nt][0], acc[mt][nt][1]);
            float2 v1 = make_float2(acc[mt][nt][2], acc[mt][nt][3]);
            if (EPI == 1) {
                float2 ax = *(const float2*)(aux + col);
                v0.x += ax.x; v0.y += ax.y;
                v1.x += ax.x; v1.y += ax.y;
            }
            if (EPI == 2) {
                float2 ax = *(const float2*)(aux + col);
                v0.x += 2.f * ax.x; v0.y += 2.f * ax.y;
                v1.x += 2.f * ax.x; v1.y += 2.f * ax.y;
                v0.x = (v0.x > 20.f) ? v0.x : log1pf(__expf(v0.x));
                v0.y = (v0.y > 20.f) ? v0.y : log1pf(__expf(v0.y));
                v1.x = (v1.x > 20.f) ? v1.x : log1pf(__expf(v1.x));
                v1.y = (v1.y > 20.f) ? v1.y : log1pf(__expf(v1.y));
            }
            *(float2*)(C + (size_t)r0 * N + col)       = v0;
            *(float2*)(C + (size_t)(r0 + 8) * N + col) = v1;
        }
    }
}

// =================== small-N tf32 mma GEMM (N=96 path) =====================
// 128x128 CTA, warp tile 64x32, K-tile 32, 2-stage.  NG guards N.
#define SREG 136
#define ATILE (32 * SREG)
#define STG   (2 * ATILE)

__global__ __launch_bounds__(256)
void mma_gemm_n96(const float* __restrict__ A, const float* __restrict__ B,
                  float* __restrict__ C, int M, int N, int K)
{
    extern __shared__ float sm[];

    const int tid  = threadIdx.x;
    const int wid  = tid >> 5;
    const int lane = tid & 31;
    const int g    = lane >> 2;
    const int t4   = lane & 3;
    const int wm   = wid & 1;
    const int wn   = wid >> 1;

    const int brow = blockIdx.y * 128;
    const int bcol = 0;
    const int NT   = K >> 5;

    const int arow = tid & 127;
    const int kseg = (tid >> 7) * 16;
    const float* gA = A + (size_t)(brow + arow) * K + kseg;

    float acc[4][4][4];
#pragma unroll
    for (int i = 0; i < 4; i++)
#pragma unroll
        for (int j = 0; j < 4; j++)
#pragma unroll
            for (int c = 0; c < 4; c++) acc[i][j][c] = 0.f;

    float abuf[16];

    auto ldgA = [&](int kt) {
#pragma unroll
        for (int i = 0; i < 4; i++)
            *(float4*)(abuf + 4 * i) =
                *(const float4*)(gA + (size_t)kt * 32 + 4 * i);
    };
    auto stsA = [&](int stage) {
        uint32_t* dst = (uint32_t*)(sm + stage * STG);
#pragma unroll
        for (int j = 0; j < 16; j++)
            dst[(kseg + j) * SREG + arow] = f2tf32(abuf[j]);
    };
    auto cpB = [&](int stage, int kt) {
        float* dstb = sm + stage * STG + ATILE;
#pragma unroll
        for (int i = 0; i < 4; i++) {
            int c  = tid + i * 256;
            int rw = c >> 5;
            int cl = (c & 31) * 4;
            const float* src = B + (size_t)(kt * 32 + rw) * N + cl;
            uint32_t da = smem_u32(dstb + rw * SREG + cl);
            int sz = (cl < N) ? 16 : 0;
            asm volatile("cp.async.cg.shared.global [%0], [%1], 16, %2;"
                         :: "r"(da), "l"(src), "r"(sz));
        }
    };
    auto compute = [&](int stage) {
        const uint32_t* asu = (const uint32_t*)(sm + stage * STG);
        const float*    bsf = sm + stage * STG + ATILE;
#pragma unroll
        for (int kk = 0; kk < 4; kk++) {
            int kr = kk * 8 + t4;
            uint32_t af[4][4];
#pragma unroll
            for (int mt = 0; mt < 4; mt++) {
                int m0 = wm * 64 + mt * 16 + g;
                af[mt][0] = asu[kr * SREG + m0];
                af[mt][1] = asu[kr * SREG + m0 + 8];
                af[mt][2] = asu[(kr + 4) * SREG + m0];
                af[mt][3] = asu[(kr + 4) * SREG + m0 + 8];
            }
            uint32_t bf[4][2];
#pragma unroll
            for (int nt = 0; nt < 4; nt++) {
                int n0 = wn * 32 + nt * 8 + g;
                bf[nt][0] = f2tf32(bsf[kr * SREG + n0]);
                bf[nt][1] = f2tf32(bsf[(kr + 4) * SREG + n0]);
            }
#pragma unroll
            for (int mt = 0; mt < 4; mt++)
#pragma unroll
                for (int nt = 0; nt < 4; nt++)
                    mma8(acc[mt][nt], af[mt], bf[nt]);
        }
    };

    ldgA(0);
    cpB(0, 0);
    asm volatile("cp.async.commit_group;");
    stsA(0);
    asm volatile("cp.async.wait_group 0;");
    __syncthreads();

    for (int kt = 0; kt < NT; kt++) {
        int nxt = kt + 1;
        if (nxt < NT) {
            ldgA(nxt);
            cpB(nxt & 1, nxt);
            asm volatile("cp.async.commit_group;");
        }
        compute(kt & 1);
        if (nxt < NT) {
            stsA(nxt & 1);
            asm volatile("cp.async.wait_group 0;");
        }
        __syncthreads();
    }

#pragma unroll
    for (int mt = 0; mt < 4; mt++) {
        int r0 = brow + wm * 64 + mt * 16 + g;
#pragma unroll
        for (int nt = 0; nt < 4; nt++) {
            int col = bcol + wn * 32 + nt * 8 + 2 * t4;
            if (col < N) {
                *(float2*)(C + (size_t)r0 * N + col) =
                    make_float2(acc[mt][nt][0], acc[mt][nt][1]);
                *(float2*)(C + (size_t)(r0 + 8) * N + col) =
                    make_float2(acc[mt][nt][2], acc[mt][nt][3]);
            }
        }
    }
}

// ---------------- depthwise conv (k=4, SAME: pad lo=1 hi=2) + SiLU ---------
__global__ __launch_bounds__(256)
void dwconv_silu_kernel(const float* __restrict__ src, int src_ld,
                        const float* __restrict__ w, const float* __restrict__ bias,
                        float* __restrict__ dst, int dst_ld)
{
    int idx = blockIdx.x * blockDim.x + threadIdx.x;
    if (idx >= B_SZ * SEQ_L * D_HALF) return;
    int c = idx & (D_HALF - 1);
    int t = (idx >> 10) & (SEQ_L - 1);
    int b = idx >> 21;

    const float* srow = src + (size_t)b * SEQ_L * src_ld + c;
    float acc = bias[c];
#pragma unroll
    for (int j = 0; j < 4; j++) {
        int tt = t - 1 + j;
        if (tt >= 0 && tt < SEQ_L)
            acc = fmaf(srow[(size_t)tt * src_ld], w[j * D_HALF + c], acc);
    }
    float s = acc * (1.f / (1.f + __expf(-acc)));
    dst[(size_t)b * SEQ_L * dst_ld + (size_t)t * dst_ld + c] = s;
}

// ---------------- selective scan (32-thread blocks, 128 blocks) ------------
__global__ __launch_bounds__(32)
void scan_kernel(const float* __restrict__ delta,
                 const float* __restrict__ u,
                 const float* __restrict__ xdbl,
                 const float* __restrict__ Dp,
                 float* __restrict__ ycat)
{
    int b = blockIdx.x >> 5;                              // 0..3
    int d = ((blockIdx.x & 31) << 5) + threadIdx.x;       // 0..1023

    const float* dptr = delta + (size_t)b * SEQ_L * D_HALF + d;
    const float* uptr = u     + (size_t)b * SEQ_L * D_HALF + d;
    const float* bc   = xdbl  + (size_t)b * SEQ_L * 96 + DT_RANK;
    float*       yptr = ycat  + (size_t)b * SEQ_L * D_INNER + d;

    __shared__ float sBC[2][4][32];

    float h[16];
#pragma unroll
    for (int n = 0; n < 16; n++) h[n] = 0.f;
    float Dd = Dp[d];

    for (int e = threadIdx.x; e < 128; e += 32)
        sBC[0][e >> 5][e & 31] = bc[(size_t)(e >> 5) * 96 + (e & 31)];
    float dl[4], uu[4];
#pragma unroll
    for (int j = 0; j < 4; j++) {
        dl[j] = dptr[(size_t)j * D_HALF];
        uu[j] = uptr[(size_t)j * D_HALF];
    }
    __syncwarp();

    for (int tg = 0; tg < SEQ_L; tg += 4) {
        int cb = (tg >> 2) & 1, nb = cb ^ 1;
        float dl2[4] = {0.f, 0.f, 0.f, 0.f}, uu2[4] = {0.f, 0.f, 0.f, 0.f};
        if (tg + 4 < SEQ_L) {
            for (int e = threadIdx.x; e < 128; e += 32)
                sBC[nb][e >> 5][e & 31] = bc[(size_t)(tg + 4 + (e >> 5)) * 96 + (e & 31)];
#pragma unroll
            for (int j2 = 0; j2 < 4; j2++) {
                dl2[j2] = dptr[(size_t)(tg + 4 + j2) * D_HALF];
                uu2[j2] = uptr[(size_t)(tg + 4 + j2) * D_HALF];
            }
        }
#pragma unroll
        for (int j = 0; j < 4; j++) {
            float del = dl[j], uv = uu[j];
            float e1 = __expf(-del);
            float e2 = e1 * e1;
            float e3 = e2 * e1;
            float e4 = e2 * e2;
            float dbu = del * uv;
            const float* Bv = sBC[cb][j];
            float a0 = 0.f, a1 = 0.f, a2 = 0.f, a3 = 0.f;
            float pw = 1.f;
#pragma unroll
            for (int gg = 0; gg < 4; gg++) {
                float q1 = pw * e1, q2 = pw * e2, q3 = pw * e3, q4 = pw * e4;
                int n = gg * 4;
                h[n]     = fmaf(q1, h[n],     dbu * Bv[n]);     a0 = fmaf(h[n],     Bv[16 + n],     a0);
                h[n + 1] = fmaf(q2, h[n + 1], dbu * Bv[n + 1]); a1 = fmaf(h[n + 1], Bv[16 + n + 1], a1);
                h[n + 2] = fmaf(q3, h[n + 2], dbu * Bv[n + 2]); a2 = fmaf(h[n + 2], Bv[16 + n + 2], a2);
                h[n + 3] = fmaf(q4, h[n + 3], dbu * Bv[n + 3]); a3 = fmaf(h[n + 3], Bv[16 + n + 3], a3);
                pw = q4;
            }
            yptr[(size_t)(tg + j) * D_INNER] = (a0 + a1) + (a2 + a3) + uv * Dd;
        }
#pragma unroll
        for (int j = 0; j < 4; j++) { dl[j] = dl2[j]; uu[j] = uu2[j]; }
        __syncwarp();
    }
}

// ---------------- launch ----------------------------------------------------
extern "C" void kernel_launch(void* const* d_in, const int* in_sizes, int n_in,
                              void* d_out, int out_size)
{
    const float* x       = (const float*)d_in[0];
    const float* W_in    = (const float*)d_in[1];
    const float* conv_xw = (const float*)d_in[2];
    const float* conv_xb = (const float*)d_in[3];
    const float* conv_zw = (const float*)d_in[4];
    const float* conv_zb = (const float*)d_in[5];
    const float* W_xdbl  = (const float*)d_in[6];
    const float* W_dt    = (const float*)d_in[7];
    const float* inv_dt  = (const float*)d_in[8];
    const float* Dp      = (const float*)d_in[9];
    const float* W_out   = (const float*)d_in[10];
    const float* b_out   = (const float*)d_in[11];
    float* out = (float*)d_out;

    float *p_xz, *p_xsc, *p_xdbl, *p_delta, *p_cat;
    cudaGetSymbolAddress((void**)&p_xz,    g_xz);
    cudaGetSymbolAddress((void**)&p_xsc,   g_xsc);
    cudaGetSymbolAddress((void**)&p_xdbl,  g_xdbl);
    cudaGetSymbolAddress((void**)&p_delta, g_delta);
    cudaGetSymbolAddress((void**)&p_cat,   g_cat);

    const int SMEM_BIG = 4 * 7296 * 4;   // 4 stages * 7296 floats = 116736 B
    const int SMEM_N96 = 2 * STG * 4;    // 69632 B
    cudaFuncSetAttribute(mma_gemm_big<0>, cudaFuncAttributeMaxDynamicSharedMemorySize, SMEM_BIG);
    cudaFuncSetAttribute(mma_gemm_big<1>, cudaFuncAttributeMaxDynamicSharedMemorySize, SMEM_BIG);
    cudaFuncSetAttribute(mma_gemm_big<2>, cudaFuncAttributeMaxDynamicSharedMemorySize, SMEM_BIG);
    cudaFuncSetAttribute(mma_gemm_n96,    cudaFuncAttributeMaxDynamicSharedMemorySize, SMEM_N96);

    // 1) xz = x @ W_in   (8192 x 2048, K=1024)
    mma_gemm_big<0><<<dim3(D_INNER / 128, M_ROWS / 256), 256, SMEM_BIG>>>(
        x, W_in, p_xz, M_ROWS, D_INNER, D_MODEL, D_MODEL, nullptr);

    // 2) convs + silu
    int nconv = B_SZ * SEQ_L * D_HALF;
    dwconv_silu_kernel<<<(nconv + 255) / 256, 256>>>(
        p_xz, D_INNER, conv_xw, conv_xb, p_xsc, D_HALF);
    dwconv_silu_kernel<<<(nconv + 255) / 256, 256>>>(
        p_xz + D_HALF, D_INNER, conv_zw, conv_zb, p_cat + D_HALF, D_INNER);

    // 3) x_dbl = xs_c @ W_xdbl   (8192 x 96, K=1024)
    mma_gemm_n96<<<dim3(1, M_ROWS / 128), 256, SMEM_N96>>>(
        p_xsc, W_xdbl, p_xdbl, M_ROWS, 96, D_HALF);

    // 4) delta = softplus(dt_low @ W_dt + 2*inv_dt)   (8192 x 1024, K=64, lda=96)
    mma_gemm_big<2><<<dim3(D_HALF / 128, M_ROWS / 256), 256, SMEM_BIG>>>(
        p_xdbl, W_dt, p_delta, M_ROWS, D_HALF, DT_RANK, 96, inv_dt);

    // 5) selective scan -> cat[:, :1024]
    scan_kernel<<<B_SZ * 32, 32>>>(p_delta, p_xsc, p_xdbl, Dp, p_cat);

    // 6) out = cat @ W_out + b_out   (8192 x 1024, K=2048)
    mma_gemm_big<1><<<dim3(D_MODEL / 128, M_ROWS / 256), 256, SMEM_BIG>>>(
        p_cat, W_out, out, M_ROWS, D_MODEL, D_INNER, D_INNER, b_out);
}